// round 1
// baseline (speedup 1.0000x reference)
#include <cuda_runtime.h>
#include <cuda_bf16.h>

// Problem constants (fixed by the reference).
namespace {
constexpr int Bn = 4096;   // batch
constexpr int Tn = 32;     // theta size
constexpr int Xn = 256;    // x size
constexpr int En = 32;     // experts / masks
constexpr int Hn = 512;    // hidden
constexpr int Ln = 2;      // hidden layers
constexpr int BM = 32;     // rows per CTA
constexpr int BK = 8;      // K-tile for weight staging
constexpr int NT = 256;    // threads per CTA
}

// Fully fused per-(expert, row-tile) MLP:
//   hbuf <- [theta*mask | x]   (32 x 288)
//   layer1: hbuf(288) @ [W1t;W1x] + b1 -> PReLU -> hbuf (32 x 512)
//   2x hidden: hbuf @ Wh[l] + bh -> PReLU -> hbuf
//   out[b,e] = hbuf . Wo + bo  (shfl reduce)
// Thread micro-tile: 4 rows x 16 cols (c = tx + j*32, conflict-free LDS).
__global__ __launch_bounds__(NT, 1)
void mnre_fused(const float* __restrict__ theta, const float* __restrict__ x,
                const int*   __restrict__ masks,
                const float* __restrict__ W1t, const float* __restrict__ W1x,
                const float* __restrict__ b1,  const float* __restrict__ a1,
                const float* __restrict__ Wh,  const float* __restrict__ bh,
                const float* __restrict__ ah,
                const float* __restrict__ Wo,  const float* __restrict__ bo,
                float* __restrict__ out)
{
    __shared__ float hbuf[BM][Hn];   // 64 KB activation tile
    __shared__ float wt[BK][Hn];     // 16 KB weight staging tile

    const int e   = blockIdx.y;
    const int m0  = blockIdx.x * BM;
    const int tid = threadIdx.x;
    const int tx  = tid & 31;        // lane
    const int wy  = tid >> 5;        // warp 0..7
    const int r0  = wy * 4;          // this thread's first row

    // ---- stage inputs: hbuf[m][0:32] = theta * mask(e), hbuf[m][32:288] = x
    for (int i = tid; i < BM * Tn; i += NT) {
        const int m = i >> 5, k = i & 31;
        hbuf[m][k] = theta[(size_t)(m0 + m) * Tn + k] * (float)masks[e * Tn + k];
    }
    for (int i = tid; i < BM * Xn; i += NT) {
        const int m = i >> 8, k = i & 255;
        hbuf[m][Tn + k] = x[(size_t)(m0 + m) * Xn + k];
    }

    float acc[4][16];

    // ================= layer 1: K = 288 =================
    {
        const float* bias = b1 + (size_t)e * Hn;
        #pragma unroll
        for (int j = 0; j < 16; j++) {
            const float bv = bias[tx + j * 32];
            #pragma unroll
            for (int r = 0; r < 4; r++) acc[r][j] = bv;
        }
        for (int k0 = 0; k0 < Tn + Xn; k0 += BK) {
            __syncthreads();   // previous wt reads / hbuf writes complete
            #pragma unroll
            for (int it = 0; it < (BK * (Hn / 4)) / NT; it++) {
                const int f  = tid + it * NT;
                const int kr = f >> 7, c4 = f & 127;
                const int kg = k0 + kr;
                const float* src = (kg < Tn)
                    ? (W1t + (size_t)(e * Tn + kg) * Hn)
                    : (W1x + (size_t)(e * Xn + (kg - Tn)) * Hn);
                reinterpret_cast<float4*>(wt[kr])[c4] =
                    reinterpret_cast<const float4*>(src)[c4];
            }
            __syncthreads();
            #pragma unroll
            for (int kk = 0; kk < BK; kk++) {
                float a[4], w[16];
                #pragma unroll
                for (int r = 0; r < 4; r++) a[r] = hbuf[r0 + r][k0 + kk];
                #pragma unroll
                for (int j = 0; j < 16; j++) w[j] = wt[kk][tx + j * 32];
                #pragma unroll
                for (int r = 0; r < 4; r++)
                    #pragma unroll
                    for (int j = 0; j < 16; j++)
                        acc[r][j] = fmaf(a[r], w[j], acc[r][j]);
            }
        }
        __syncthreads();       // all hbuf reads done before overwrite
        const float* slope = a1 + (size_t)e * Hn;
        #pragma unroll
        for (int j = 0; j < 16; j++) {
            const int c = tx + j * 32;
            const float s = slope[c];
            #pragma unroll
            for (int r = 0; r < 4; r++) {
                const float v = acc[r][j];
                hbuf[r0 + r][c] = (v >= 0.f) ? v : s * v;
            }
        }
    }

    // ================= hidden layers: K = 512 =================
    for (int l = 0; l < Ln; l++) {
        const float* Wl    = Wh + (size_t)(l * En + e) * Hn * Hn;
        const float* bias  = bh + (size_t)(l * En + e) * Hn;
        const float* slope = ah + (size_t)(l * En + e) * Hn;
        #pragma unroll
        for (int j = 0; j < 16; j++) {
            const float bv = bias[tx + j * 32];
            #pragma unroll
            for (int r = 0; r < 4; r++) acc[r][j] = bv;
        }
        for (int k0 = 0; k0 < Hn; k0 += BK) {
            __syncthreads();
            #pragma unroll
            for (int it = 0; it < (BK * (Hn / 4)) / NT; it++) {
                const int f  = tid + it * NT;
                const int kr = f >> 7, c4 = f & 127;
                reinterpret_cast<float4*>(wt[kr])[c4] =
                    reinterpret_cast<const float4*>(Wl + (size_t)(k0 + kr) * Hn)[c4];
            }
            __syncthreads();
            #pragma unroll
            for (int kk = 0; kk < BK; kk++) {
                float a[4], w[16];
                #pragma unroll
                for (int r = 0; r < 4; r++) a[r] = hbuf[r0 + r][k0 + kk];
                #pragma unroll
                for (int j = 0; j < 16; j++) w[j] = wt[kk][tx + j * 32];
                #pragma unroll
                for (int r = 0; r < 4; r++)
                    #pragma unroll
                    for (int j = 0; j < 16; j++)
                        acc[r][j] = fmaf(a[r], w[j], acc[r][j]);
            }
        }
        __syncthreads();
        #pragma unroll
        for (int j = 0; j < 16; j++) {
            const int c = tx + j * 32;
            const float s = slope[c];
            #pragma unroll
            for (int r = 0; r < 4; r++) {
                const float v = acc[r][j];
                hbuf[r0 + r][c] = (v >= 0.f) ? v : s * v;
            }
        }
    }
    __syncthreads();

    // ================= output: dot with Wo, shfl reduce =================
    {
        const float* wo = Wo + (size_t)e * Hn;
        float partial[4] = {0.f, 0.f, 0.f, 0.f};
        #pragma unroll
        for (int j = 0; j < 16; j++) {
            const int c = tx + j * 32;
            const float wv = wo[c];
            #pragma unroll
            for (int r = 0; r < 4; r++)
                partial[r] = fmaf(hbuf[r0 + r][c], wv, partial[r]);
        }
        const float bov = bo[e];
        #pragma unroll
        for (int r = 0; r < 4; r++) {
            float s = partial[r];
            #pragma unroll
            for (int off = 16; off > 0; off >>= 1)
                s += __shfl_xor_sync(0xffffffffu, s, off);
            if (tx == 0)
                out[(size_t)(m0 + r0 + r) * En + e] = s + bov;
        }
    }
}

extern "C" void kernel_launch(void* const* d_in, const int* in_sizes, int n_in,
                              void* d_out, int out_size) {
    const float* theta = (const float*)d_in[0];
    const float* x     = (const float*)d_in[1];
    const int*   masks = (const int*)  d_in[2];
    const float* W1t   = (const float*)d_in[3];
    const float* W1x   = (const float*)d_in[4];
    const float* b1    = (const float*)d_in[5];
    const float* a1    = (const float*)d_in[6];
    const float* Wh    = (const float*)d_in[7];
    const float* bh    = (const float*)d_in[8];
    const float* ah    = (const float*)d_in[9];
    const float* Wo    = (const float*)d_in[10];
    const float* bo    = (const float*)d_in[11];
    float* out = (float*)d_out;

    dim3 grid(Bn / BM, En);   // 128 x 32 = 4096 CTAs
    mnre_fused<<<grid, NT>>>(theta, x, masks, W1t, W1x, b1, a1,
                             Wh, bh, ah, Wo, bo, out);
}

// round 3
// speedup vs baseline: 2.7337x; 2.7337x over previous
#include <cuda_runtime.h>
#include <cuda_bf16.h>
#include <cstdint>

namespace {
constexpr int Bn = 4096;   // batch
constexpr int Tn = 32;     // theta size
constexpr int Xn = 256;    // x size
constexpr int En = 32;     // experts
constexpr int Hn = 512;    // hidden
constexpr int Ln = 2;      // hidden layers
constexpr int BM = 32;     // rows per CTA
constexpr int BK = 16;     // K-chunk for weight staging
constexpr int NT = 256;    // threads per CTA
constexpr int HP = 516;    // hbuf row stride (pad 4 -> conflict-free A frags)
constexpr int WP = 520;    // wt row stride  (pad 8 -> conflict-free B frags)
constexpr int SMEM_BYTES = (BM * HP + BK * WP) * 4;  // 66048 + 33280 = 99328
}

__device__ __forceinline__ uint32_t tf32r(float f) {
    uint32_t r;
    asm("cvt.rna.tf32.f32 %0, %1;" : "=r"(r) : "f"(f));
    return r;
}

__device__ __forceinline__ void mma_tf32(float c[4],
                                         uint32_t a0, uint32_t a1, uint32_t a2, uint32_t a3,
                                         uint32_t b0, uint32_t b1) {
    asm volatile(
        "mma.sync.aligned.m16n8k8.row.col.f32.tf32.tf32.f32 "
        "{%0,%1,%2,%3}, {%4,%5,%6,%7}, {%8,%9}, {%0,%1,%2,%3};\n"
        : "+f"(c[0]), "+f"(c[1]), "+f"(c[2]), "+f"(c[3])
        : "r"(a0), "r"(a1), "r"(a2), "r"(a3), "r"(b0), "r"(b1));
}

__global__ __launch_bounds__(NT, 2)
void mnre_tf32(const float* __restrict__ theta, const float* __restrict__ x,
               const int*   __restrict__ masks,
               const float* __restrict__ W1t, const float* __restrict__ W1x,
               const float* __restrict__ b1,  const float* __restrict__ a1,
               const float* __restrict__ Wh,  const float* __restrict__ bh,
               const float* __restrict__ ah,
               const float* __restrict__ Wo,  const float* __restrict__ bo,
               float* __restrict__ out)
{
    extern __shared__ float smem[];
    float* hb = smem;                 // [BM][HP] activations (tf32-valued fp32)
    float* wt = smem + BM * HP;       // [BK][WP] staged weights (tf32-valued)

    const int e   = blockIdx.y;
    const int m0  = blockIdx.x * BM;
    const int tid = threadIdx.x;
    const int lane = tid & 31;
    const int wy   = tid >> 5;        // warp 0..7
    const int g    = lane >> 2;       // group id 0..7
    const int t    = lane & 3;        // thread in group
    const int nbase = wy * 64;        // this warp's N slice

    // ---- stage inputs (tf32-rounded): hb[m][0:32]=theta*mask, [32:288]=x
    for (int i = tid; i < BM * Tn; i += NT) {
        const int m = i >> 5, k = i & 31;
        const float v = theta[(size_t)(m0 + m) * Tn + k] * (float)masks[e * Tn + k];
        hb[m * HP + k] = __uint_as_float(tf32r(v));
    }
    for (int i = tid; i < BM * Xn; i += NT) {
        const int m = i >> 8, k = i & 255;
        hb[m * HP + Tn + k] = __uint_as_float(tf32r(x[(size_t)(m0 + m) * Xn + k]));
    }

    float c[2][8][4];   // [mtile][nblock][frag]

    for (int layer = 0; layer < 1 + Ln; layer++) {
        const int K = (layer == 0) ? (Tn + Xn) : Hn;
        const float* bias;
        const float* slope;
        const float* Wl = nullptr;
        if (layer == 0) {
            bias  = b1 + (size_t)e * Hn;
            slope = a1 + (size_t)e * Hn;
        } else {
            const int l = layer - 1;
            Wl    = Wh + (size_t)(l * En + e) * Hn * Hn;
            bias  = bh + (size_t)(l * En + e) * Hn;
            slope = ah + (size_t)(l * En + e) * Hn;
        }

        // init accumulators with bias
        #pragma unroll
        for (int nb = 0; nb < 8; nb++) {
            const int col0 = nbase + nb * 8 + 2 * t;
            const float bv0 = bias[col0], bv1 = bias[col0 + 1];
            #pragma unroll
            for (int mt = 0; mt < 2; mt++) {
                c[mt][nb][0] = bv0; c[mt][nb][1] = bv1;
                c[mt][nb][2] = bv0; c[mt][nb][3] = bv1;
            }
        }

        for (int k0 = 0; k0 < K; k0 += BK) {
            __syncthreads();   // wt free / hb input ready
            // stage BK x 512 weights, tf32-rounded
            #pragma unroll
            for (int it = 0; it < (BK * (Hn / 4)) / NT; it++) {
                const int f  = tid + it * NT;
                const int kr = f >> 7, c4 = f & 127;
                const float* src;
                if (layer == 0) {
                    const int kg = k0 + kr;
                    src = (kg < Tn) ? (W1t + (size_t)(e * Tn + kg) * Hn)
                                    : (W1x + (size_t)(e * Xn + (kg - Tn)) * Hn);
                } else {
                    src = Wl + (size_t)(k0 + kr) * Hn;
                }
                const float4 v = reinterpret_cast<const float4*>(src)[c4];
                float4 o;
                o.x = __uint_as_float(tf32r(v.x));
                o.y = __uint_as_float(tf32r(v.y));
                o.z = __uint_as_float(tf32r(v.z));
                o.w = __uint_as_float(tf32r(v.w));
                reinterpret_cast<float4*>(wt + kr * WP)[c4] = o;
            }
            __syncthreads();

            #pragma unroll
            for (int s = 0; s < BK / 8; s++) {
                const int ka = k0 + s * 8;   // hb column
                const int kw = s * 8;        // wt row
                uint32_t a[2][4];
                #pragma unroll
                for (int mt = 0; mt < 2; mt++) {
                    const int r = mt * 16 + g;
                    a[mt][0] = __float_as_uint(hb[r * HP + ka + t]);
                    a[mt][1] = __float_as_uint(hb[(r + 8) * HP + ka + t]);
                    a[mt][2] = __float_as_uint(hb[r * HP + ka + t + 4]);
                    a[mt][3] = __float_as_uint(hb[(r + 8) * HP + ka + t + 4]);
                }
                #pragma unroll
                for (int nb = 0; nb < 8; nb++) {
                    const int col = nbase + nb * 8 + g;
                    const uint32_t b0 = __float_as_uint(wt[(kw + t) * WP + col]);
                    const uint32_t b1 = __float_as_uint(wt[(kw + t + 4) * WP + col]);
                    mma_tf32(c[0][nb], a[0][0], a[0][1], a[0][2], a[0][3], b0, b1);
                    mma_tf32(c[1][nb], a[1][0], a[1][1], a[1][2], a[1][3], b0, b1);
                }
            }
        }

        __syncthreads();   // all hb reads for this layer done
        // epilogue: PReLU, tf32-round, write back to hb
        #pragma unroll
        for (int nb = 0; nb < 8; nb++) {
            const int col0 = nbase + nb * 8 + 2 * t;
            const float s0 = slope[col0], s1 = slope[col0 + 1];
            #pragma unroll
            for (int mt = 0; mt < 2; mt++) {
                const int r = mt * 16 + g;
                float v0 = c[mt][nb][0]; v0 = (v0 >= 0.f) ? v0 : s0 * v0;
                float v1 = c[mt][nb][1]; v1 = (v1 >= 0.f) ? v1 : s1 * v1;
                float v2 = c[mt][nb][2]; v2 = (v2 >= 0.f) ? v2 : s0 * v2;
                float v3 = c[mt][nb][3]; v3 = (v3 >= 0.f) ? v3 : s1 * v3;
                hb[r * HP + col0]           = __uint_as_float(tf32r(v0));
                hb[r * HP + col0 + 1]       = __uint_as_float(tf32r(v1));
                hb[(r + 8) * HP + col0]     = __uint_as_float(tf32r(v2));
                hb[(r + 8) * HP + col0 + 1] = __uint_as_float(tf32r(v3));
            }
        }
    }
    __syncthreads();

    // ---- output: dot with Wo, shfl reduce (fp32)
    {
        const float* wo = Wo + (size_t)e * Hn;
        const int r0 = wy * 4;
        float partial[4] = {0.f, 0.f, 0.f, 0.f};
        #pragma unroll
        for (int j = 0; j < 16; j++) {
            const int cidx = lane + j * 32;
            const float wv = wo[cidx];
            #pragma unroll
            for (int r = 0; r < 4; r++)
                partial[r] = fmaf(hb[(r0 + r) * HP + cidx], wv, partial[r]);
        }
        const float bov = bo[e];
        #pragma unroll
        for (int r = 0; r < 4; r++) {
            float s = partial[r];
            #pragma unroll
            for (int off = 16; off > 0; off >>= 1)
                s += __shfl_xor_sync(0xffffffffu, s, off);
            if (lane == 0)
                out[(size_t)(m0 + r0 + r) * En + e] = s + bov;
        }
    }
}

extern "C" void kernel_launch(void* const* d_in, const int* in_sizes, int n_in,
                              void* d_out, int out_size) {
    const float* theta = (const float*)d_in[0];
    const float* x     = (const float*)d_in[1];
    const int*   masks = (const int*)  d_in[2];
    const float* W1t   = (const float*)d_in[3];
    const float* W1x   = (const float*)d_in[4];
    const float* b1    = (const float*)d_in[5];
    const float* a1    = (const float*)d_in[6];
    const float* Wh    = (const float*)d_in[7];
    const float* bh    = (const float*)d_in[8];
    const float* ah    = (const float*)d_in[9];
    const float* Wo    = (const float*)d_in[10];
    const float* bo    = (const float*)d_in[11];
    float* out = (float*)d_out;

    cudaFuncSetAttribute(mnre_tf32, cudaFuncAttributeMaxDynamicSharedMemorySize,
                         SMEM_BYTES);
    dim3 grid(Bn / BM, En);   // 128 x 32 = 4096 CTAs
    mnre_tf32<<<grid, NT, SMEM_BYTES>>>(theta, x, masks, W1t, W1x, b1, a1,
                                        Wh, bh, ah, Wo, bo, out);
}

// round 4
// speedup vs baseline: 3.5834x; 1.3108x over previous
#include <cuda_runtime.h>
#include <cuda_bf16.h>
#include <cstdint>

namespace {
constexpr int Bn = 4096;   // batch
constexpr int Tn = 32;     // theta size
constexpr int Xn = 256;    // x size
constexpr int En = 32;     // experts
constexpr int Hn = 512;    // hidden
constexpr int Ln = 2;      // hidden layers
constexpr int BM = 64;     // rows per CTA
constexpr int BK = 16;     // K-chunk for weight staging
constexpr int NT = 512;    // threads per CTA (16 warps: 2 x 8)
constexpr int HP = 516;    // hbuf row stride (pad 4 -> conflict-free A frags)
constexpr int WP = 520;    // wt row stride  (pad 8 -> conflict-free B frags)
constexpr int WTBUF = BK * WP;                            // floats per wt buffer
constexpr int SMEM_BYTES = (BM * HP + 2 * WTBUF) * 4;     // 132096 + 66560 = 198656
}

__device__ __forceinline__ uint32_t tf32r(float f) {
    uint32_t r;
    asm("cvt.rna.tf32.f32 %0, %1;" : "=r"(r) : "f"(f));
    return r;
}

__device__ __forceinline__ void mma_tf32(float c[4],
                                         uint32_t a0, uint32_t a1, uint32_t a2, uint32_t a3,
                                         uint32_t b0, uint32_t b1) {
    asm volatile(
        "mma.sync.aligned.m16n8k8.row.col.f32.tf32.tf32.f32 "
        "{%0,%1,%2,%3}, {%4,%5,%6,%7}, {%8,%9}, {%0,%1,%2,%3};\n"
        : "+f"(c[0]), "+f"(c[1]), "+f"(c[2]), "+f"(c[3])
        : "r"(a0), "r"(a1), "r"(a2), "r"(a3), "r"(b0), "r"(b1));
}

__global__ __launch_bounds__(NT, 1)
void mnre_tf32p(const float* __restrict__ theta, const float* __restrict__ x,
                const int*   __restrict__ masks,
                const float* __restrict__ W1t, const float* __restrict__ W1x,
                const float* __restrict__ b1,  const float* __restrict__ a1,
                const float* __restrict__ Wh,  const float* __restrict__ bh,
                const float* __restrict__ ah,
                const float* __restrict__ Wo,  const float* __restrict__ bo,
                float* __restrict__ out)
{
    extern __shared__ float smem[];
    float* hb  = smem;                 // [BM][HP] activations (tf32-valued fp32)
    float* wtb = smem + BM * HP;       // 2 x [BK][WP] double-buffered weights

    const int e    = blockIdx.y;
    const int m0   = blockIdx.x * BM;
    const int tid  = threadIdx.x;
    const int lane = tid & 31;
    const int wy   = tid >> 5;         // warp 0..15
    const int warpM = wy >> 3;         // 0..1
    const int warpN = wy & 7;          // 0..7
    const int g    = lane >> 2;        // 0..7
    const int t    = lane & 3;         // 0..3
    const int nbase = warpN * 64;
    const int mbase = warpM * 32;

    // ---- stage inputs (tf32-rounded): hb[m][0:32]=theta*mask, [32:288]=x
    #pragma unroll
    for (int it = 0; it < (BM * Tn) / NT; it++) {
        const int i = tid + it * NT;
        const int m = i >> 5, k = i & 31;
        const float v = theta[(size_t)(m0 + m) * Tn + k] * (float)masks[e * Tn + k];
        hb[m * HP + k] = __uint_as_float(tf32r(v));
    }
    #pragma unroll 4
    for (int it = 0; it < (BM * Xn) / NT; it++) {
        const int i = tid + it * NT;
        const int m = i >> 8, k = i & 255;
        hb[m * HP + Tn + k] = __uint_as_float(tf32r(x[(size_t)(m0 + m) * Xn + k]));
    }

    float  c[2][8][4];   // [mtile][nblock][frag]
    float4 stg[4];       // in-flight next weight chunk (16 floats)

    for (int layer = 0; layer < 1 + Ln; layer++) {
        const int K = (layer == 0) ? (Tn + Xn) : Hn;
        const int nch = K / BK;
        const float* bias;
        const float* slope;
        const float* Wl = nullptr;
        if (layer == 0) {
            bias  = b1 + (size_t)e * Hn;
            slope = a1 + (size_t)e * Hn;
        } else {
            const int l = layer - 1;
            Wl    = Wh + (size_t)(l * En + e) * Hn * Hn;
            bias  = bh + (size_t)(l * En + e) * Hn;
            slope = ah + (size_t)(l * En + e) * Hn;
        }

        // --- chunk loaders (4 float4 per thread cover BK x 512) ---
        auto ldg_chunk = [&](int k0) {
            #pragma unroll
            for (int it = 0; it < 4; it++) {
                const int f  = tid + it * NT;
                const int kr = f >> 7, c4 = f & 127;
                const float* src;
                if (layer == 0) {
                    const int kg = k0 + kr;
                    src = (kg < Tn) ? (W1t + (size_t)(e * Tn + kg) * Hn)
                                    : (W1x + (size_t)(e * Xn + (kg - Tn)) * Hn);
                } else {
                    src = Wl + (size_t)(k0 + kr) * Hn;
                }
                stg[it] = reinterpret_cast<const float4*>(src)[c4];
            }
        };
        auto sts_chunk = [&](int buf) {
            float* w = wtb + buf * WTBUF;
            #pragma unroll
            for (int it = 0; it < 4; it++) {
                const int f  = tid + it * NT;
                const int kr = f >> 7, c4 = f & 127;
                float4 v = stg[it], o;
                o.x = __uint_as_float(tf32r(v.x));
                o.y = __uint_as_float(tf32r(v.y));
                o.z = __uint_as_float(tf32r(v.z));
                o.w = __uint_as_float(tf32r(v.w));
                reinterpret_cast<float4*>(w + kr * WP)[c4] = o;
            }
        };

        // init accumulators with bias
        #pragma unroll
        for (int nb = 0; nb < 8; nb++) {
            const int col0 = nbase + nb * 8 + 2 * t;
            const float bv0 = bias[col0], bv1 = bias[col0 + 1];
            #pragma unroll
            for (int mt = 0; mt < 2; mt++) {
                c[mt][nb][0] = bv0; c[mt][nb][1] = bv1;
                c[mt][nb][2] = bv0; c[mt][nb][3] = bv1;
            }
        }

        // prologue: chunk 0 into buffer 0
        ldg_chunk(0);
        sts_chunk(0);
        int buf = 0;

        for (int ci = 0; ci < nch; ci++) {
            if (ci + 1 < nch) ldg_chunk((ci + 1) * BK);   // prefetch next
            __syncthreads();                               // wt[buf] + hb visible

            const float* w = wtb + buf * WTBUF;
            const int k0 = ci * BK;
            #pragma unroll
            for (int s = 0; s < BK / 8; s++) {
                const int ka = k0 + s * 8;   // hb column
                const int kw = s * 8;        // wt row
                uint32_t a[2][4];
                #pragma unroll
                for (int mt = 0; mt < 2; mt++) {
                    const int r = mbase + mt * 16 + g;
                    a[mt][0] = __float_as_uint(hb[r * HP + ka + t]);
                    a[mt][1] = __float_as_uint(hb[(r + 8) * HP + ka + t]);
                    a[mt][2] = __float_as_uint(hb[r * HP + ka + t + 4]);
                    a[mt][3] = __float_as_uint(hb[(r + 8) * HP + ka + t + 4]);
                }
                #pragma unroll
                for (int nb = 0; nb < 8; nb++) {
                    const int col = nbase + nb * 8 + g;
                    const uint32_t b0 = __float_as_uint(w[(kw + t) * WP + col]);
                    const uint32_t b1 = __float_as_uint(w[(kw + t + 4) * WP + col]);
                    mma_tf32(c[0][nb], a[0][0], a[0][1], a[0][2], a[0][3], b0, b1);
                    mma_tf32(c[1][nb], a[1][0], a[1][1], a[1][2], a[1][3], b0, b1);
                }
            }

            if (ci + 1 < nch) sts_chunk(buf ^ 1);   // fill other buffer
            buf ^= 1;
        }

        __syncthreads();   // all hb reads for this layer done
        // epilogue: PReLU, tf32-round, write back to hb
        #pragma unroll
        for (int nb = 0; nb < 8; nb++) {
            const int col0 = nbase + nb * 8 + 2 * t;
            const float s0 = slope[col0], s1 = slope[col0 + 1];
            #pragma unroll
            for (int mt = 0; mt < 2; mt++) {
                const int r = mbase + mt * 16 + g;
                float v0 = c[mt][nb][0]; v0 = (v0 >= 0.f) ? v0 : s0 * v0;
                float v1 = c[mt][nb][1]; v1 = (v1 >= 0.f) ? v1 : s1 * v1;
                float v2 = c[mt][nb][2]; v2 = (v2 >= 0.f) ? v2 : s0 * v2;
                float v3 = c[mt][nb][3]; v3 = (v3 >= 0.f) ? v3 : s1 * v3;
                hb[r * HP + col0]           = __uint_as_float(tf32r(v0));
                hb[r * HP + col0 + 1]       = __uint_as_float(tf32r(v1));
                hb[(r + 8) * HP + col0]     = __uint_as_float(tf32r(v2));
                hb[(r + 8) * HP + col0 + 1] = __uint_as_float(tf32r(v3));
            }
        }
    }
    __syncthreads();

    // ---- output: dot with Wo, shfl reduce (fp32)
    {
        const float* wo = Wo + (size_t)e * Hn;
        const int r0 = wy * 4;   // 16 warps x 4 rows = 64
        float partial[4] = {0.f, 0.f, 0.f, 0.f};
        #pragma unroll
        for (int j = 0; j < 16; j++) {
            const int cidx = lane + j * 32;
            const float wv = wo[cidx];
            #pragma unroll
            for (int r = 0; r < 4; r++)
                partial[r] = fmaf(hb[(r0 + r) * HP + cidx], wv, partial[r]);
        }
        const float bov = bo[e];
        #pragma unroll
        for (int r = 0; r < 4; r++) {
            float s = partial[r];
            #pragma unroll
            for (int off = 16; off > 0; off >>= 1)
                s += __shfl_xor_sync(0xffffffffu, s, off);
            if (lane == 0)
                out[(size_t)(m0 + r0 + r) * En + e] = s + bov;
        }
    }
}

extern "C" void kernel_launch(void* const* d_in, const int* in_sizes, int n_in,
                              void* d_out, int out_size) {
    const float* theta = (const float*)d_in[0];
    const float* x     = (const float*)d_in[1];
    const int*   masks = (const int*)  d_in[2];
    const float* W1t   = (const float*)d_in[3];
    const float* W1x   = (const float*)d_in[4];
    const float* b1    = (const float*)d_in[5];
    const float* a1    = (const float*)d_in[6];
    const float* Wh    = (const float*)d_in[7];
    const float* bh    = (const float*)d_in[8];
    const float* ah    = (const float*)d_in[9];
    const float* Wo    = (const float*)d_in[10];
    const float* bo    = (const float*)d_in[11];
    float* out = (float*)d_out;

    cudaFuncSetAttribute(mnre_tf32p, cudaFuncAttributeMaxDynamicSharedMemorySize,
                         SMEM_BYTES);
    dim3 grid(Bn / BM, En);   // 64 x 32 = 2048 CTAs
    mnre_tf32p<<<grid, NT, SMEM_BYTES>>>(theta, x, masks, W1t, W1x, b1, a1,
                                         Wh, bh, ah, Wo, bo, out);
}

// round 5
// speedup vs baseline: 4.3160x; 1.2044x over previous
#include <cuda_runtime.h>
#include <cuda_bf16.h>
#include <cstdint>

namespace {
constexpr int Bn = 4096;   // batch
constexpr int Tn = 32;     // theta size
constexpr int Xn = 256;    // x size
constexpr int En = 32;     // experts
constexpr int Hn = 512;    // hidden
constexpr int Ln = 2;      // hidden layers
constexpr int BM = 64;     // rows per CTA
constexpr int BK = 16;     // K-chunk
constexpr int NT = 512;    // threads per CTA (16 warps: 2 x 8)
constexpr int HP = 516;    // hbuf row stride (conflict-free A frags)
constexpr int WP = 520;    // weight row stride (conflict-free B frags)
constexpr int WTBUF = BK * WP;                         // floats per buffer (8320)
constexpr int CHUNK_BYTES = WTBUF * 4;                 // 33280, %16 == 0
constexpr int SMEM_BYTES = (BM * HP + 2 * WTBUF) * 4;  // 132096 + 66560 = 198656
constexpr int RPE = Tn + Xn + Ln * Hn;                 // rows per expert = 1312
}

// Pre-rounded, pre-padded tf32 weights: [E][1312 rows][520] (row-major).
// Rows 0..287 = layer1 ([W1t;W1x]), 288..799 = Wh[0], 800..1311 = Wh[1].
__device__ float wscratch[(size_t)En * RPE * WP];

__device__ __forceinline__ uint32_t tf32r(float f) {
    uint32_t r;
    asm("cvt.rna.tf32.f32 %0, %1;" : "=r"(r) : "f"(f));
    return r;
}

__device__ __forceinline__ void mma_tf32(float c[4],
                                         uint32_t a0, uint32_t a1, uint32_t a2, uint32_t a3,
                                         uint32_t b0, uint32_t b1) {
    asm volatile(
        "mma.sync.aligned.m16n8k8.row.col.f32.tf32.tf32.f32 "
        "{%0,%1,%2,%3}, {%4,%5,%6,%7}, {%8,%9}, {%0,%1,%2,%3};\n"
        : "+f"(c[0]), "+f"(c[1]), "+f"(c[2]), "+f"(c[3])
        : "r"(a0), "r"(a1), "r"(a2), "r"(a3), "r"(b0), "r"(b1));
}

__device__ __forceinline__ void mbar_init(uint32_t mbar, uint32_t cnt) {
    asm volatile("mbarrier.init.shared.b64 [%0], %1;" :: "r"(mbar), "r"(cnt) : "memory");
}
__device__ __forceinline__ void mbar_expect_tx(uint32_t mbar, uint32_t bytes) {
    asm volatile("mbarrier.arrive.expect_tx.shared.b64 _, [%0], %1;"
                 :: "r"(mbar), "r"(bytes) : "memory");
}
__device__ __forceinline__ void bulk_g2s(uint32_t dst, const void* src,
                                         uint32_t bytes, uint32_t mbar) {
    asm volatile(
        "cp.async.bulk.shared::cta.global.mbarrier::complete_tx::bytes "
        "[%0], [%1], %2, [%3];"
        :: "r"(dst), "l"(src), "r"(bytes), "r"(mbar) : "memory");
}
__device__ __forceinline__ void mbar_wait(uint32_t mbar, uint32_t phase) {
    uint32_t done;
    do {
        asm volatile(
            "{\n\t.reg .pred p;\n\t"
            "mbarrier.try_wait.parity.acquire.cta.shared::cta.b64 p, [%1], %2, 0x989680;\n\t"
            "selp.b32 %0, 1, 0, p;\n\t}"
            : "=r"(done) : "r"(mbar), "r"(phase) : "memory");
    } while (!done);
}

// ---------- prep: round all weights to tf32 into wscratch (padded layout) ----
__global__ void mnre_prep(const float* __restrict__ W1t, const float* __restrict__ W1x,
                          const float* __restrict__ Wh) {
    const int row = blockIdx.x;          // 0 .. En*RPE-1
    const int e   = row / RPE;
    const int r   = row % RPE;
    const int c4  = threadIdx.x;         // 0..129 (float4 index in 520-wide row)
    float4 o = make_float4(0.f, 0.f, 0.f, 0.f);
    if (c4 < Hn / 4) {
        const float* src;
        if (r < Tn)            src = W1t + ((size_t)(e * Tn + r) * Hn);
        else if (r < Tn + Xn)  src = W1x + ((size_t)(e * Xn + (r - Tn)) * Hn);
        else {
            const int rr = r - (Tn + Xn);
            const int l  = rr / Hn;
            const int k  = rr % Hn;
            src = Wh + ((size_t)(l * En + e) * Hn + k) * Hn;
        }
        const float4 v = reinterpret_cast<const float4*>(src)[c4];
        o.x = __uint_as_float(tf32r(v.x));
        o.y = __uint_as_float(tf32r(v.y));
        o.z = __uint_as_float(tf32r(v.z));
        o.w = __uint_as_float(tf32r(v.w));
    }
    reinterpret_cast<float4*>(wscratch + (size_t)row * WP)[c4] = o;
}

// ---------- main fused kernel ------------------------------------------------
__global__ __launch_bounds__(NT, 1)
void mnre_tf32t(const float* __restrict__ theta, const float* __restrict__ x,
                const int*   __restrict__ masks,
                const float* __restrict__ b1,  const float* __restrict__ a1,
                const float* __restrict__ bh,  const float* __restrict__ ah,
                const float* __restrict__ Wo,  const float* __restrict__ bo,
                float* __restrict__ out)
{
    extern __shared__ float smem[];
    float* hb  = smem;                 // [BM][HP] activations (tf32-valued fp32)
    float* wtb = smem + BM * HP;       // 2 x [BK][WP] double-buffered weights
    __shared__ alignas(8) unsigned long long mbars[2];

    const int e    = blockIdx.y;
    const int m0   = blockIdx.x * BM;
    const int tid  = threadIdx.x;
    const int lane = tid & 31;
    const int wy   = tid >> 5;         // warp 0..15
    const int warpM = wy >> 3;         // 0..1
    const int warpN = wy & 7;          // 0..7
    const int g    = lane >> 2;        // 0..7
    const int t    = lane & 3;         // 0..3
    const int nbase = warpN * 64;
    const int mbase = warpM * 32;

    const uint32_t bar0 = (uint32_t)__cvta_generic_to_shared(&mbars[0]);
    const uint32_t bar1 = (uint32_t)__cvta_generic_to_shared(&mbars[1]);
    const float* wexp = wscratch + (size_t)e * RPE * WP;
    const uint32_t wtb0 = (uint32_t)__cvta_generic_to_shared(wtb);

    if (tid == 0) {
        mbar_init(bar0, 1);
        mbar_init(bar1, 1);
        asm volatile("fence.proxy.async.shared::cta;" ::: "memory");
    }
    __syncthreads();

    int buf = 0;
    uint32_t phbits = 0;   // per-buffer wait parity

    // kick off layer-0 chunk 0 while we stage the inputs
    if (tid == 0) {
        mbar_expect_tx(bar0, CHUNK_BYTES);
        bulk_g2s(wtb0, wexp, CHUNK_BYTES, bar0);
    }

    // ---- stage inputs (tf32-rounded): hb[m][0:32]=theta*mask, [32:288]=x
    #pragma unroll
    for (int it = 0; it < (BM * Tn) / NT; it++) {
        const int i = tid + it * NT;
        const int m = i >> 5, k = i & 31;
        const float v = theta[(size_t)(m0 + m) * Tn + k] * (float)masks[e * Tn + k];
        hb[m * HP + k] = __uint_as_float(tf32r(v));
    }
    #pragma unroll 4
    for (int it = 0; it < (BM * Xn) / NT; it++) {
        const int i = tid + it * NT;
        const int m = i >> 8, k = i & 255;
        hb[m * HP + Tn + k] = __uint_as_float(tf32r(x[(size_t)(m0 + m) * Xn + k]));
    }

    float c[2][8][4];   // [mtile][nblock][frag]

    int rowoff = 0;     // row offset of current layer inside wexp
    for (int layer = 0; layer < 1 + Ln; layer++) {
        const int K   = (layer == 0) ? (Tn + Xn) : Hn;
        const int nch = K / BK;
        const float* bias;
        const float* slope;
        if (layer == 0) {
            bias  = b1 + (size_t)e * Hn;
            slope = a1 + (size_t)e * Hn;
        } else {
            const int l = layer - 1;
            bias  = bh + (size_t)(l * En + e) * Hn;
            slope = ah + (size_t)(l * En + e) * Hn;
        }
        const float* wlayer = wexp + (size_t)rowoff * WP;

        // chunk 0 of layers > 0 (layer 0 already in flight)
        if (layer > 0 && tid == 0) {
            const uint32_t b = buf ? bar1 : bar0;
            mbar_expect_tx(b, CHUNK_BYTES);
            bulk_g2s(wtb0 + buf * CHUNK_BYTES, wlayer, CHUNK_BYTES, b);
        }

        // init accumulators with bias
        #pragma unroll
        for (int nb = 0; nb < 8; nb++) {
            const int col0 = nbase + nb * 8 + 2 * t;
            const float bv0 = bias[col0], bv1 = bias[col0 + 1];
            #pragma unroll
            for (int mt = 0; mt < 2; mt++) {
                c[mt][nb][0] = bv0; c[mt][nb][1] = bv1;
                c[mt][nb][2] = bv0; c[mt][nb][3] = bv1;
            }
        }

        for (int ci = 0; ci < nch; ci++) {
            // wait for this chunk's data
            const uint32_t barc = buf ? bar1 : bar0;
            mbar_wait(barc, (phbits >> buf) & 1u);
            phbits ^= (1u << buf);
            __syncthreads();   // all warps past previous compute on buf^1

            // prefetch next chunk into the other buffer
            if (ci + 1 < nch && tid == 0) {
                const int nb2 = buf ^ 1;
                const uint32_t barn = nb2 ? bar1 : bar0;
                mbar_expect_tx(barn, CHUNK_BYTES);
                bulk_g2s(wtb0 + nb2 * CHUNK_BYTES,
                         wlayer + (size_t)(ci + 1) * WTBUF, CHUNK_BYTES, barn);
            }

            const float* w = wtb + buf * WTBUF;
            const int k0 = ci * BK;
            #pragma unroll
            for (int s = 0; s < BK / 8; s++) {
                const int ka = k0 + s * 8;   // hb column
                const int kw = s * 8;        // w row
                uint32_t a[2][4];
                #pragma unroll
                for (int mt = 0; mt < 2; mt++) {
                    const int r = mbase + mt * 16 + g;
                    a[mt][0] = __float_as_uint(hb[r * HP + ka + t]);
                    a[mt][1] = __float_as_uint(hb[(r + 8) * HP + ka + t]);
                    a[mt][2] = __float_as_uint(hb[r * HP + ka + t + 4]);
                    a[mt][3] = __float_as_uint(hb[(r + 8) * HP + ka + t + 4]);
                }
                #pragma unroll
                for (int nb = 0; nb < 8; nb++) {
                    const int col = nbase + nb * 8 + g;
                    const uint32_t b0 = __float_as_uint(w[(kw + t) * WP + col]);
                    const uint32_t b1 = __float_as_uint(w[(kw + t + 4) * WP + col]);
                    mma_tf32(c[0][nb], a[0][0], a[0][1], a[0][2], a[0][3], b0, b1);
                    mma_tf32(c[1][nb], a[1][0], a[1][1], a[1][2], a[1][3], b0, b1);
                }
            }
            buf ^= 1;
        }
        rowoff += K;

        __syncthreads();   // all hb reads for this layer done
        // epilogue: PReLU, tf32-round, write back to hb
        #pragma unroll
        for (int nb = 0; nb < 8; nb++) {
            const int col0 = nbase + nb * 8 + 2 * t;
            const float s0 = slope[col0], s1 = slope[col0 + 1];
            #pragma unroll
            for (int mt = 0; mt < 2; mt++) {
                const int r = mbase + mt * 16 + g;
                float v0 = c[mt][nb][0]; v0 = (v0 >= 0.f) ? v0 : s0 * v0;
                float v1 = c[mt][nb][1]; v1 = (v1 >= 0.f) ? v1 : s1 * v1;
                float v2 = c[mt][nb][2]; v2 = (v2 >= 0.f) ? v2 : s0 * v2;
                float v3 = c[mt][nb][3]; v3 = (v3 >= 0.f) ? v3 : s1 * v3;
                hb[r * HP + col0]           = __uint_as_float(tf32r(v0));
                hb[r * HP + col0 + 1]       = __uint_as_float(tf32r(v1));
                hb[(r + 8) * HP + col0]     = __uint_as_float(tf32r(v2));
                hb[(r + 8) * HP + col0 + 1] = __uint_as_float(tf32r(v3));
            }
        }
    }
    __syncthreads();

    // ---- output: dot with Wo, shfl reduce (fp32)
    {
        const float* wo = Wo + (size_t)e * Hn;
        const int r0 = wy * 4;   // 16 warps x 4 rows = 64
        float partial[4] = {0.f, 0.f, 0.f, 0.f};
        #pragma unroll
        for (int j = 0; j < 16; j++) {
            const int cidx = lane + j * 32;
            const float wv = wo[cidx];
            #pragma unroll
            for (int r = 0; r < 4; r++)
                partial[r] = fmaf(hb[(r0 + r) * HP + cidx], wv, partial[r]);
        }
        const float bov = bo[e];
        #pragma unroll
        for (int r = 0; r < 4; r++) {
            float s = partial[r];
            #pragma unroll
            for (int off = 16; off > 0; off >>= 1)
                s += __shfl_xor_sync(0xffffffffu, s, off);
            if (lane == 0)
                out[(size_t)(m0 + r0 + r) * En + e] = s + bov;
        }
    }
}

extern "C" void kernel_launch(void* const* d_in, const int* in_sizes, int n_in,
                              void* d_out, int out_size) {
    const float* theta = (const float*)d_in[0];
    const float* x     = (const float*)d_in[1];
    const int*   masks = (const int*)  d_in[2];
    const float* W1t   = (const float*)d_in[3];
    const float* W1x   = (const float*)d_in[4];
    const float* b1    = (const float*)d_in[5];
    const float* a1    = (const float*)d_in[6];
    const float* Wh    = (const float*)d_in[7];
    const float* bh    = (const float*)d_in[8];
    const float* ah    = (const float*)d_in[9];
    const float* Wo    = (const float*)d_in[10];
    const float* bo    = (const float*)d_in[11];
    float* out = (float*)d_out;

    // 1) pre-round weights into tiled scratch (one block per 520-wide row)
    mnre_prep<<<En * RPE, 130>>>(W1t, W1x, Wh);

    // 2) fused MLP
    cudaFuncSetAttribute(mnre_tf32t, cudaFuncAttributeMaxDynamicSharedMemorySize,
                         SMEM_BYTES);
    dim3 grid(Bn / BM, En);   // 64 x 32 = 2048 CTAs
    mnre_tf32t<<<grid, NT, SMEM_BYTES>>>(theta, x, masks, b1, a1,
                                         bh, ah, Wo, bo, out);
}